// round 10
// baseline (speedup 1.0000x reference)
#include <cuda_runtime.h>
#include <math.h>
#include <stdint.h>

#define BB 32
#define SS 128
#define UU 256
#define HH 128
#define VV 30001

// Scratch (__device__ globals: allocation-free rule)
__device__ float g_state[BB * UU * HH];   // per-(b,u) hidden state
__device__ float g_outs[BB * SS * HH];    // RNN outputs (tf32-rounded) = GEMM A

__device__ __forceinline__ float to_tf32(float x) {
    float r;
    asm("cvt.rna.tf32.f32 %0, %1;" : "=f"(r) : "f"(x));
    return r;
}

// f32x2 packed math (sm_103a)
__device__ __forceinline__ unsigned long long pack2(float lo, float hi) {
    unsigned long long d;
    asm("mov.b64 %0, {%1, %2};" : "=l"(d) : "f"(lo), "f"(hi));
    return d;
}
__device__ __forceinline__ void unpack2(unsigned long long v, float& lo, float& hi) {
    asm("mov.b64 {%0, %1}, %2;" : "=f"(lo), "=f"(hi) : "l"(v));
}
__device__ __forceinline__ void fma2(unsigned long long& d, unsigned long long a,
                                     unsigned long long b) {
    asm("fma.rn.f32x2 %0, %1, %2, %0;" : "+l"(d) : "l"(a), "l"(b));
}

// ===========================================================================
// RNN scan (unchanged from R8 passing version)
// ===========================================================================
#define CH 16
#define TP 20

#define RNN_F_WRU   (128 * 256)
#define RNN_F_WC    (128 * 128)
#define RNN_F_BUFS  (3 * 128 * TP)
#define RNN_INTS    (128 + 128 + 128 + 128 + 130 + 8)
#define RNN_SMEM_BYTES ((RNN_F_WRU + RNN_F_WC + 256 + 128 + RNN_F_BUFS + RNN_INTS) * 4)

__global__ __launch_bounds__(256, 1) void rnn_kernel(
    const int* __restrict__ users, const int* __restrict__ items,
    const float* __restrict__ h0,
    const float* __restrict__ P_ru, const float* __restrict__ W_ru,
    const float* __restrict__ b_ru, const float* __restrict__ P_c,
    const float* __restrict__ W_c,  const float* __restrict__ b_c)
{
    extern __shared__ float sm[];
    float* sWru = sm;
    float* sWc  = sWru + RNN_F_WRU;
    float* sbru = sWc + RNN_F_WC;
    float* sbc  = sbru + 256;
    float* sHT  = sbc + 128;
    float* sRHT = sHT + 128 * TP;
    float* sZT  = sRHT + 128 * TP;
    int*   su      = (int*)(sZT + 128 * TP);
    int*   sit     = su + 128;
    int*   slev    = sit + 128;
    int*   sorder  = slev + 128;
    int*   slstart = sorder + 128;
    int*   smisc   = slstart + 130;

    const int b   = blockIdx.x;
    const int tid = threadIdx.x;

    {
        const float4* s4 = (const float4*)W_ru;
        float4*       d4 = (float4*)sWru;
        for (int i = tid; i < RNN_F_WRU / 4; i += 256) d4[i] = s4[i];
        const float4* s4c = (const float4*)W_c;
        float4*       d4c = (float4*)sWc;
        for (int i = tid; i < RNN_F_WC / 4; i += 256) d4c[i] = s4c[i];
    }
    sbru[tid] = b_ru[tid];
    if (tid < HH) sbc[tid] = b_c[tid];

    for (int i = tid; i < 3 * 128 * TP; i += 256) sHT[i] = 0.0f;

    {
        const float4* src = (const float4*)(h0 + (size_t)b * UU * HH);
        float4*       dst = (float4*)(g_state + (size_t)b * UU * HH);
        for (int i = tid; i < UU * HH / 4; i += 256) dst[i] = src[i];
    }

    if (tid < SS) {
        su[tid]  = users[b * SS + tid];
        sit[tid] = items[b * SS + tid];
    }
    __syncthreads();

    if (tid < SS) {
        int u = su[tid], c = 0;
        for (int tp = 0; tp < tid; tp++) c += (su[tp] == u);
        slev[tid] = c;
    }
    __syncthreads();
    if (tid == 0) {
        int m = 0;
        for (int t = 0; t < SS; t++) m = max(m, slev[t]);
        smisc[0] = m + 1;
    }
    if (tid <= SS) {
        int c = 0;
        for (int t = 0; t < SS; t++) c += (slev[t] < tid);
        slstart[tid] = c;
    }
    __syncthreads();
    if (tid < SS) {
        int l = slev[tid], r = 0;
        for (int tp = 0; tp < tid; tp++) r += (slev[tp] == l);
        sorder[slstart[l] + r] = tid;
    }
    __syncthreads();

    const int maxlev = smisc[0];
    float* state_b = g_state + (size_t)b * UU * HH;
    float* out_b   = g_outs + (size_t)b * SS * HH;
    const int j = tid;

    for (int l = 0; l < maxlev; l++) {
        const int lstart = slstart[l], lend = slstart[l + 1];
        for (int cs = lstart; cs < lend; cs += CH) {
            const int n = min(CH, lend - cs);

            {
                int i      = tid & 15;
                int r4base = tid >> 4;
                if (i < n) {
                    int t = sorder[cs + i];
                    const float4* srcs = (const float4*)(state_b + su[t] * HH);
                    #pragma unroll
                    for (int rr = 0; rr < 2; rr++) {
                        int r4 = r4base + rr * 16;
                        float4 v = srcs[r4];
                        int k0 = r4 * 4;
                        sHT[(k0 + 0) * TP + i] = v.x;
                        sHT[(k0 + 1) * TP + i] = v.y;
                        sHT[(k0 + 2) * TP + i] = v.z;
                        sHT[(k0 + 3) * TP + i] = v.w;
                    }
                }
            }
            __syncthreads();

            {
                float pAdd[CH];
                #pragma unroll
                for (int i = 0; i < CH; i++) pAdd[i] = 0.0f;
                for (int i = 0; i < n; i++)
                    pAdd[i] = P_ru[(size_t)sit[sorder[cs + i]] * (2 * HH) + j];

                unsigned long long acc2[CH / 2];
                #pragma unroll
                for (int p = 0; p < CH / 2; p++) acc2[p] = 0ULL;

                #pragma unroll 4
                for (int k = 0; k < HH; k++) {
                    float w = sWru[k * 256 + j];
                    unsigned long long w2 = pack2(w, w);
                    const ulonglong2* h4 = (const ulonglong2*)(sHT + k * TP);
                    #pragma unroll
                    for (int q = 0; q < CH / 4; q++) {
                        ulonglong2 hp = h4[q];
                        fma2(acc2[2 * q],     hp.x, w2);
                        fma2(acc2[2 * q + 1], hp.y, w2);
                    }
                }

                float bj = sbru[j];
                if (j < HH) {
                    #pragma unroll
                    for (int p = 0; p < CH / 2; p++) {
                        float a0, a1;
                        unpack2(acc2[p], a0, a1);
                        float x0 = fminf(fmaxf(a0 + pAdd[2 * p] + bj,     -15.f), 15.f);
                        float x1 = fminf(fmaxf(a1 + pAdd[2 * p + 1] + bj, -15.f), 15.f);
                        float r0 = __fdividef(1.0f, 1.0f + __expf(-x0));
                        float r1 = __fdividef(1.0f, 1.0f + __expf(-x1));
                        sRHT[j * TP + 2 * p]     = r0 * sHT[j * TP + 2 * p];
                        sRHT[j * TP + 2 * p + 1] = r1 * sHT[j * TP + 2 * p + 1];
                    }
                } else {
                    int jz = j - HH;
                    #pragma unroll
                    for (int p = 0; p < CH / 2; p++) {
                        float a0, a1;
                        unpack2(acc2[p], a0, a1);
                        float x0 = fminf(fmaxf(a0 + pAdd[2 * p] + bj,     -15.f), 15.f);
                        float x1 = fminf(fmaxf(a1 + pAdd[2 * p + 1] + bj, -15.f), 15.f);
                        sZT[jz * TP + 2 * p]     = __fdividef(1.0f, 1.0f + __expf(-x0));
                        sZT[jz * TP + 2 * p + 1] = __fdividef(1.0f, 1.0f + __expf(-x1));
                    }
                }
            }
            __syncthreads();

            if (j < HH) {
                float pAdd[CH];
                #pragma unroll
                for (int i = 0; i < CH; i++) pAdd[i] = 0.0f;
                for (int i = 0; i < n; i++)
                    pAdd[i] = P_c[(size_t)sit[sorder[cs + i]] * HH + j];

                unsigned long long acc2[CH / 2];
                #pragma unroll
                for (int p = 0; p < CH / 2; p++) acc2[p] = 0ULL;

                #pragma unroll 4
                for (int k = 0; k < HH; k++) {
                    float w = sWc[k * 128 + j];
                    unsigned long long w2 = pack2(w, w);
                    const ulonglong2* r4 = (const ulonglong2*)(sRHT + k * TP);
                    #pragma unroll
                    for (int q = 0; q < CH / 4; q++) {
                        ulonglong2 rp = r4[q];
                        fma2(acc2[2 * q],     rp.x, w2);
                        fma2(acc2[2 * q + 1], rp.y, w2);
                    }
                }

                float bj = sbc[j];
                float cc[CH];
                #pragma unroll
                for (int p = 0; p < CH / 2; p++) {
                    float a0, a1;
                    unpack2(acc2[p], a0, a1);
                    float x0 = fminf(fmaxf(a0 + pAdd[2 * p] + bj,     -15.f), 15.f);
                    float x1 = fminf(fmaxf(a1 + pAdd[2 * p + 1] + bj, -15.f), 15.f);
                    float t0 = __expf(-2.0f * x0);
                    float t1 = __expf(-2.0f * x1);
                    cc[2 * p]     = __fdividef(1.0f - t0, 1.0f + t0);
                    cc[2 * p + 1] = __fdividef(1.0f - t1, 1.0f + t1);
                }
                for (int i = 0; i < n; i++) {
                    int t = sorder[cs + i];
                    float z = sZT[j * TP + i];
                    float h = sHT[j * TP + i];
                    float hn = z * h + (1.0f - z) * cc[i];
                    state_b[su[t] * HH + j] = hn;
                    out_b[(size_t)t * HH + j] = to_tf32(hn);
                }
            }
            __syncthreads();
        }
    }
}

// ===========================================================================
// Logits GEMM, mma.sync tf32 (tcgen05 NOT available at this PTX target).
//   512 threads (16 warps = 4/SMSP), warp tile 32m x 32n.
//   B stored pre-packed in fragment order: float2(B[k][c], B[k+4][c])
//   -> 4 LDS.64 per warp k-step instead of 16 LDS.32.
//   A double-buffered via cp.async across 8 M-subtiles.
// ===========================================================================
#define APITCH 132
// smem: B packed 16*512 float2 (64KB) + A 2*128*APITCH floats (132KB)
#define G_NB2   (16 * 512)                 // float2 count for B
#define G_SMEM_BYTES (G_NB2 * 8 + 2 * 128 * APITCH * 4)

__device__ __forceinline__ void cp_async16(uint32_t saddr, const void* gsrc) {
    asm volatile("cp.async.cg.shared.global [%0], [%1], 16;\n" :: "r"(saddr), "l"(gsrc));
}
__device__ __forceinline__ void cp_commit() { asm volatile("cp.async.commit_group;\n"); }
__device__ __forceinline__ void cp_wait0()  { asm volatile("cp.async.wait_group 0;\n"); }

__device__ __forceinline__ void mma_tf32(float c[4], const unsigned a[4],
                                         const unsigned bfr[2]) {
    asm volatile(
        "mma.sync.aligned.m16n8k8.row.col.f32.tf32.tf32.f32 "
        "{%0,%1,%2,%3}, {%4,%5,%6,%7}, {%8,%9}, {%0,%1,%2,%3};\n"
        : "+f"(c[0]), "+f"(c[1]), "+f"(c[2]), "+f"(c[3])
        : "r"(a[0]), "r"(a[1]), "r"(a[2]), "r"(a[3]), "r"(bfr[0]), "r"(bfr[1]));
}

__global__ __launch_bounds__(512, 1) void gemm_kernel(const float* __restrict__ ws,
                                                      float* __restrict__ out)
{
    extern __shared__ float smg[];
    float2* sBp = (float2*)smg;                    // [16ks][128c][4lc] float2
    float*  sA  = smg + G_NB2 * 2;                 // [2][128][APITCH]

    const int tid = threadIdx.x;
    const int n0  = blockIdx.x * 128;
    const int mg  = blockIdx.y * 1024;

    uint32_t sA_base = (uint32_t)__cvta_generic_to_shared(sA);

    // ---- prefetch A subtile 0 into buf 0 ----
    {
        const float* src = g_outs + (size_t)mg * HH;
        for (int idx = tid; idx < 128 * 32; idx += 512) {
            int row = idx >> 5, q = idx & 31;
            cp_async16(sA_base + (row * APITCH + q * 4) * 4, src + row * HH + q * 4);
        }
        cp_commit();
    }

    // ---- B load, packed fragment order, tf32-rounded in-flight ----
    // idx -> c (fast, coalesced), lc, ks.  k = ks*8+lc; pair (k, k+4).
    for (int idx = tid; idx < 16 * 128 * 4; idx += 512) {
        int c  = idx & 127;
        int lc = (idx >> 7) & 3;
        int ks = idx >> 9;
        int k  = ks * 8 + lc;
        int gn = n0 + c;
        float v0 = 0.0f, v1 = 0.0f;
        if (gn < VV) {
            v0 = ws[(size_t)k * VV + gn];
            v1 = ws[(size_t)(k + 4) * VV + gn];
        }
        sBp[ks * 512 + c * 4 + lc] = make_float2(to_tf32(v0), to_tf32(v1));
    }

    const int wid  = tid >> 5;
    const int lane = tid & 31;
    const int wm = (wid & 3) * 32;     // warp m-offset (4 warps over 128 m)
    const int wn = (wid >> 2) * 32;    // warp n-offset (4 warps over 128 n)
    const int lr = lane >> 2;
    const int lc = lane & 3;

    cp_wait0();
    __syncthreads();

    int buf = 0;
    for (int msub = 0; msub < 8; msub++) {
        if (msub < 7) {
            const float* src = g_outs + (size_t)(mg + (msub + 1) * 128) * HH;
            uint32_t dstb = sA_base + (uint32_t)(buf ^ 1) * 128u * APITCH * 4u;
            for (int idx = tid; idx < 128 * 32; idx += 512) {
                int row = idx >> 5, q = idx & 31;
                cp_async16(dstb + (row * APITCH + q * 4) * 4, src + row * HH + q * 4);
            }
            cp_commit();
        }

        float* sAc = sA + buf * 128 * APITCH;

        float acc[2][4][4];
        #pragma unroll
        for (int mt = 0; mt < 2; mt++)
            #pragma unroll
            for (int nt = 0; nt < 4; nt++)
                #pragma unroll
                for (int q = 0; q < 4; q++) acc[mt][nt][q] = 0.0f;

        #pragma unroll
        for (int ks = 0; ks < 16; ks++) {
            const int k0 = ks * 8;
            unsigned a[2][4];
            #pragma unroll
            for (int mt = 0; mt < 2; mt++) {
                int r = wm + mt * 16 + lr;
                a[mt][0] = __float_as_uint(sAc[r * APITCH + k0 + lc]);
                a[mt][1] = __float_as_uint(sAc[(r + 8) * APITCH + k0 + lc]);
                a[mt][2] = __float_as_uint(sAc[r * APITCH + k0 + lc + 4]);
                a[mt][3] = __float_as_uint(sAc[(r + 8) * APITCH + k0 + lc + 4]);
            }
            unsigned bfr[4][2];
            #pragma unroll
            for (int nt = 0; nt < 4; nt++) {
                int c = wn + nt * 8 + lr;
                float2 bp = sBp[ks * 512 + c * 4 + lc];   // LDS.64
                bfr[nt][0] = __float_as_uint(bp.x);
                bfr[nt][1] = __float_as_uint(bp.y);
            }
            #pragma unroll
            for (int mt = 0; mt < 2; mt++)
                #pragma unroll
                for (int nt = 0; nt < 4; nt++)
                    mma_tf32(acc[mt][nt], a[mt], bfr[nt]);
        }

        const int m0 = mg + msub * 128;
        #pragma unroll
        for (int mt = 0; mt < 2; mt++) {
            #pragma unroll
            for (int nt = 0; nt < 4; nt++) {
                int r = m0 + wm + mt * 16 + lr;
                int c = n0 + wn + nt * 8 + lc * 2;
                if (c < VV) {
                    out[(size_t)r * VV + c]       = acc[mt][nt][0];
                    out[(size_t)(r + 8) * VV + c] = acc[mt][nt][2];
                }
                if (c + 1 < VV) {
                    out[(size_t)r * VV + c + 1]       = acc[mt][nt][1];
                    out[(size_t)(r + 8) * VV + c + 1] = acc[mt][nt][3];
                }
            }
        }

        cp_wait0();
        __syncthreads();
        buf ^= 1;
    }
}

// ---------------------------------------------------------------------------
// launch
// ---------------------------------------------------------------------------
extern "C" void kernel_launch(void* const* d_in, const int* in_sizes, int n_in,
                              void* d_out, int out_size)
{
    const int*   users = (const int*)d_in[0];
    const int*   items = (const int*)d_in[1];
    const float* h0    = (const float*)d_in[2];
    const float* P_ru  = (const float*)d_in[3];
    const float* W_ru  = (const float*)d_in[4];
    const float* b_ru  = (const float*)d_in[5];
    const float* P_c   = (const float*)d_in[6];
    const float* W_c   = (const float*)d_in[7];
    const float* b_c   = (const float*)d_in[8];
    const float* ws    = (const float*)d_in[9];
    float* out = (float*)d_out;

    static_assert(RNN_SMEM_BYTES <= 232448, "rnn smem too big");
    static_assert(G_SMEM_BYTES <= 232448, "gemm smem too big");

    cudaFuncSetAttribute(rnn_kernel, cudaFuncAttributeMaxDynamicSharedMemorySize,
                         RNN_SMEM_BYTES);
    cudaFuncSetAttribute(gemm_kernel, cudaFuncAttributeMaxDynamicSharedMemorySize,
                         G_SMEM_BYTES);

    rnn_kernel<<<BB, 256, RNN_SMEM_BYTES>>>(users, items, h0, P_ru, W_ru, b_ru,
                                            P_c, W_c, b_c);

    dim3 grid((VV + 127) / 128, 4);
    gemm_kernel<<<grid, 512, G_SMEM_BYTES>>>(ws, out);
}

// round 11
// speedup vs baseline: 1.6188x; 1.6188x over previous
#include <cuda_runtime.h>
#include <math.h>
#include <stdint.h>

#define BB 32
#define SS 128
#define UU 256
#define HH 128
#define VV 30001

// Scratch (__device__ globals: allocation-free rule)
__device__ float g_state[BB * UU * HH];   // per-(b,u) hidden state
__device__ float g_outs[BB * SS * HH];    // RNN outputs (tf32-rounded) = GEMM A

__device__ __forceinline__ float to_tf32(float x) {
    float r;
    asm("cvt.rna.tf32.f32 %0, %1;" : "=f"(r) : "f"(x));
    return r;
}

// f32x2 packed math (sm_103a)
__device__ __forceinline__ unsigned long long pack2(float lo, float hi) {
    unsigned long long d;
    asm("mov.b64 %0, {%1, %2};" : "=l"(d) : "f"(lo), "f"(hi));
    return d;
}
__device__ __forceinline__ void unpack2(unsigned long long v, float& lo, float& hi) {
    asm("mov.b64 {%0, %1}, %2;" : "=f"(lo), "=f"(hi) : "l"(v));
}
__device__ __forceinline__ void fma2(unsigned long long& d, unsigned long long a,
                                     unsigned long long b) {
    asm("fma.rn.f32x2 %0, %1, %2, %0;" : "+l"(d) : "l"(a), "l"(b));
}

// ===========================================================================
// RNN scan (unchanged from R8 passing version)
// ===========================================================================
#define CH 16
#define TP 20

#define RNN_F_WRU   (128 * 256)
#define RNN_F_WC    (128 * 128)
#define RNN_F_BUFS  (3 * 128 * TP)
#define RNN_INTS    (128 + 128 + 128 + 128 + 130 + 8)
#define RNN_SMEM_BYTES ((RNN_F_WRU + RNN_F_WC + 256 + 128 + RNN_F_BUFS + RNN_INTS) * 4)

__global__ __launch_bounds__(256, 1) void rnn_kernel(
    const int* __restrict__ users, const int* __restrict__ items,
    const float* __restrict__ h0,
    const float* __restrict__ P_ru, const float* __restrict__ W_ru,
    const float* __restrict__ b_ru, const float* __restrict__ P_c,
    const float* __restrict__ W_c,  const float* __restrict__ b_c)
{
    extern __shared__ float sm[];
    float* sWru = sm;
    float* sWc  = sWru + RNN_F_WRU;
    float* sbru = sWc + RNN_F_WC;
    float* sbc  = sbru + 256;
    float* sHT  = sbc + 128;
    float* sRHT = sHT + 128 * TP;
    float* sZT  = sRHT + 128 * TP;
    int*   su      = (int*)(sZT + 128 * TP);
    int*   sit     = su + 128;
    int*   slev    = sit + 128;
    int*   sorder  = slev + 128;
    int*   slstart = sorder + 128;
    int*   smisc   = slstart + 130;

    const int b   = blockIdx.x;
    const int tid = threadIdx.x;

    {
        const float4* s4 = (const float4*)W_ru;
        float4*       d4 = (float4*)sWru;
        for (int i = tid; i < RNN_F_WRU / 4; i += 256) d4[i] = s4[i];
        const float4* s4c = (const float4*)W_c;
        float4*       d4c = (float4*)sWc;
        for (int i = tid; i < RNN_F_WC / 4; i += 256) d4c[i] = s4c[i];
    }
    sbru[tid] = b_ru[tid];
    if (tid < HH) sbc[tid] = b_c[tid];

    for (int i = tid; i < 3 * 128 * TP; i += 256) sHT[i] = 0.0f;

    {
        const float4* src = (const float4*)(h0 + (size_t)b * UU * HH);
        float4*       dst = (float4*)(g_state + (size_t)b * UU * HH);
        for (int i = tid; i < UU * HH / 4; i += 256) dst[i] = src[i];
    }

    if (tid < SS) {
        su[tid]  = users[b * SS + tid];
        sit[tid] = items[b * SS + tid];
    }
    __syncthreads();

    if (tid < SS) {
        int u = su[tid], c = 0;
        for (int tp = 0; tp < tid; tp++) c += (su[tp] == u);
        slev[tid] = c;
    }
    __syncthreads();
    if (tid == 0) {
        int m = 0;
        for (int t = 0; t < SS; t++) m = max(m, slev[t]);
        smisc[0] = m + 1;
    }
    if (tid <= SS) {
        int c = 0;
        for (int t = 0; t < SS; t++) c += (slev[t] < tid);
        slstart[tid] = c;
    }
    __syncthreads();
    if (tid < SS) {
        int l = slev[tid], r = 0;
        for (int tp = 0; tp < tid; tp++) r += (slev[tp] == l);
        sorder[slstart[l] + r] = tid;
    }
    __syncthreads();

    const int maxlev = smisc[0];
    float* state_b = g_state + (size_t)b * UU * HH;
    float* out_b   = g_outs + (size_t)b * SS * HH;
    const int j = tid;

    for (int l = 0; l < maxlev; l++) {
        const int lstart = slstart[l], lend = slstart[l + 1];
        for (int cs = lstart; cs < lend; cs += CH) {
            const int n = min(CH, lend - cs);

            {
                int i      = tid & 15;
                int r4base = tid >> 4;
                if (i < n) {
                    int t = sorder[cs + i];
                    const float4* srcs = (const float4*)(state_b + su[t] * HH);
                    #pragma unroll
                    for (int rr = 0; rr < 2; rr++) {
                        int r4 = r4base + rr * 16;
                        float4 v = srcs[r4];
                        int k0 = r4 * 4;
                        sHT[(k0 + 0) * TP + i] = v.x;
                        sHT[(k0 + 1) * TP + i] = v.y;
                        sHT[(k0 + 2) * TP + i] = v.z;
                        sHT[(k0 + 3) * TP + i] = v.w;
                    }
                }
            }
            __syncthreads();

            {
                float pAdd[CH];
                #pragma unroll
                for (int i = 0; i < CH; i++) pAdd[i] = 0.0f;
                for (int i = 0; i < n; i++)
                    pAdd[i] = P_ru[(size_t)sit[sorder[cs + i]] * (2 * HH) + j];

                unsigned long long acc2[CH / 2];
                #pragma unroll
                for (int p = 0; p < CH / 2; p++) acc2[p] = 0ULL;

                #pragma unroll 4
                for (int k = 0; k < HH; k++) {
                    float w = sWru[k * 256 + j];
                    unsigned long long w2 = pack2(w, w);
                    const ulonglong2* h4 = (const ulonglong2*)(sHT + k * TP);
                    #pragma unroll
                    for (int q = 0; q < CH / 4; q++) {
                        ulonglong2 hp = h4[q];
                        fma2(acc2[2 * q],     hp.x, w2);
                        fma2(acc2[2 * q + 1], hp.y, w2);
                    }
                }

                float bj = sbru[j];
                if (j < HH) {
                    #pragma unroll
                    for (int p = 0; p < CH / 2; p++) {
                        float a0, a1;
                        unpack2(acc2[p], a0, a1);
                        float x0 = fminf(fmaxf(a0 + pAdd[2 * p] + bj,     -15.f), 15.f);
                        float x1 = fminf(fmaxf(a1 + pAdd[2 * p + 1] + bj, -15.f), 15.f);
                        float r0 = __fdividef(1.0f, 1.0f + __expf(-x0));
                        float r1 = __fdividef(1.0f, 1.0f + __expf(-x1));
                        sRHT[j * TP + 2 * p]     = r0 * sHT[j * TP + 2 * p];
                        sRHT[j * TP + 2 * p + 1] = r1 * sHT[j * TP + 2 * p + 1];
                    }
                } else {
                    int jz = j - HH;
                    #pragma unroll
                    for (int p = 0; p < CH / 2; p++) {
                        float a0, a1;
                        unpack2(acc2[p], a0, a1);
                        float x0 = fminf(fmaxf(a0 + pAdd[2 * p] + bj,     -15.f), 15.f);
                        float x1 = fminf(fmaxf(a1 + pAdd[2 * p + 1] + bj, -15.f), 15.f);
                        sZT[jz * TP + 2 * p]     = __fdividef(1.0f, 1.0f + __expf(-x0));
                        sZT[jz * TP + 2 * p + 1] = __fdividef(1.0f, 1.0f + __expf(-x1));
                    }
                }
            }
            __syncthreads();

            if (j < HH) {
                float pAdd[CH];
                #pragma unroll
                for (int i = 0; i < CH; i++) pAdd[i] = 0.0f;
                for (int i = 0; i < n; i++)
                    pAdd[i] = P_c[(size_t)sit[sorder[cs + i]] * HH + j];

                unsigned long long acc2[CH / 2];
                #pragma unroll
                for (int p = 0; p < CH / 2; p++) acc2[p] = 0ULL;

                #pragma unroll 4
                for (int k = 0; k < HH; k++) {
                    float w = sWc[k * 128 + j];
                    unsigned long long w2 = pack2(w, w);
                    const ulonglong2* r4 = (const ulonglong2*)(sRHT + k * TP);
                    #pragma unroll
                    for (int q = 0; q < CH / 4; q++) {
                        ulonglong2 rp = r4[q];
                        fma2(acc2[2 * q],     rp.x, w2);
                        fma2(acc2[2 * q + 1], rp.y, w2);
                    }
                }

                float bj = sbc[j];
                float cc[CH];
                #pragma unroll
                for (int p = 0; p < CH / 2; p++) {
                    float a0, a1;
                    unpack2(acc2[p], a0, a1);
                    float x0 = fminf(fmaxf(a0 + pAdd[2 * p] + bj,     -15.f), 15.f);
                    float x1 = fminf(fmaxf(a1 + pAdd[2 * p + 1] + bj, -15.f), 15.f);
                    float t0 = __expf(-2.0f * x0);
                    float t1 = __expf(-2.0f * x1);
                    cc[2 * p]     = __fdividef(1.0f - t0, 1.0f + t0);
                    cc[2 * p + 1] = __fdividef(1.0f - t1, 1.0f + t1);
                }
                for (int i = 0; i < n; i++) {
                    int t = sorder[cs + i];
                    float z = sZT[j * TP + i];
                    float h = sHT[j * TP + i];
                    float hn = z * h + (1.0f - z) * cc[i];
                    state_b[su[t] * HH + j] = hn;
                    out_b[(size_t)t * HH + j] = to_tf32(hn);
                }
            }
            __syncthreads();
        }
    }
}

// ===========================================================================
// Logits GEMM, mma.sync tf32 — 2 CTAs/SM for cross-CTA phase overlap.
//   256 threads; CTA owns 128-wide N tile (B packed fragment order, 64 KB),
//   sweeps 32 M-subtiles of 32 rows (A cp.async double-buffered, 2x16.9 KB).
//   Warp tile 16m x 32n (2x4 warps). smem ~97 KB -> occupancy 2.
// ===========================================================================
#define MSUB   32
#define NSUB   (1024 / MSUB)             // 32 subtiles per CTA
#define APITCH 132
#define G_NB2  (16 * 512)                // B: [16ks][128c][4lc] float2 = 64 KB
#define G_A_FLOATS (2 * MSUB * APITCH)   // 2 buffers
#define G_SMEM_BYTES (G_NB2 * 8 + G_A_FLOATS * 4)

__device__ __forceinline__ void cp_async16(uint32_t saddr, const void* gsrc) {
    asm volatile("cp.async.cg.shared.global [%0], [%1], 16;\n" :: "r"(saddr), "l"(gsrc));
}
__device__ __forceinline__ void cp_commit() { asm volatile("cp.async.commit_group;\n"); }
__device__ __forceinline__ void cp_wait0()  { asm volatile("cp.async.wait_group 0;\n"); }

__device__ __forceinline__ void mma_tf32(float c[4], const unsigned a[4],
                                         const unsigned bfr[2]) {
    asm volatile(
        "mma.sync.aligned.m16n8k8.row.col.f32.tf32.tf32.f32 "
        "{%0,%1,%2,%3}, {%4,%5,%6,%7}, {%8,%9}, {%0,%1,%2,%3};\n"
        : "+f"(c[0]), "+f"(c[1]), "+f"(c[2]), "+f"(c[3])
        : "r"(a[0]), "r"(a[1]), "r"(a[2]), "r"(a[3]), "r"(bfr[0]), "r"(bfr[1]));
}

__global__ __launch_bounds__(256, 2) void gemm_kernel(const float* __restrict__ ws,
                                                      float* __restrict__ out)
{
    extern __shared__ float smg[];
    float2* sBp = (float2*)smg;              // packed B fragments
    float*  sA  = smg + G_NB2 * 2;           // [2][MSUB][APITCH]

    const int tid = threadIdx.x;
    const int n0  = blockIdx.x * 128;
    const int mg  = blockIdx.y * 1024;

    uint32_t sA_base = (uint32_t)__cvta_generic_to_shared(sA);

    // ---- prefetch A subtile 0 (32 rows x 128 k = 1024 float4) ----
    {
        const float* src = g_outs + (size_t)mg * HH;
        for (int idx = tid; idx < MSUB * 32; idx += 256) {
            int row = idx >> 5, q = idx & 31;
            cp_async16(sA_base + (row * APITCH + q * 4) * 4, src + row * HH + q * 4);
        }
        cp_commit();
    }

    // ---- B load, packed fragment order, tf32-rounded in-flight ----
    for (int idx = tid; idx < 16 * 128 * 4; idx += 256) {
        int c  = idx & 127;
        int lcc = (idx >> 7) & 3;
        int ks = idx >> 9;
        int k  = ks * 8 + lcc;
        int gn = n0 + c;
        float v0 = 0.0f, v1 = 0.0f;
        if (gn < VV) {
            v0 = ws[(size_t)k * VV + gn];
            v1 = ws[(size_t)(k + 4) * VV + gn];
        }
        sBp[ks * 512 + c * 4 + lcc] = make_float2(to_tf32(v0), to_tf32(v1));
    }

    const int wid  = tid >> 5;
    const int lane = tid & 31;
    const int wm = (wid & 1) * 16;     // 2 warps over 32 m
    const int wn = (wid >> 1) * 32;    // 4 warps over 128 n
    const int lr = lane >> 2;
    const int lc = lane & 3;

    cp_wait0();
    __syncthreads();

    int buf = 0;
    for (int msub = 0; msub < NSUB; msub++) {
        // prefetch next A subtile into the other buffer
        if (msub < NSUB - 1) {
            const float* src = g_outs + (size_t)(mg + (msub + 1) * MSUB) * HH;
            uint32_t dstb = sA_base + (uint32_t)(buf ^ 1) * (uint32_t)MSUB * APITCH * 4u;
            for (int idx = tid; idx < MSUB * 32; idx += 256) {
                int row = idx >> 5, q = idx & 31;
                cp_async16(dstb + (row * APITCH + q * 4) * 4, src + row * HH + q * 4);
            }
            cp_commit();
        }

        float* sAc = sA + buf * MSUB * APITCH;

        float acc[4][4];
        #pragma unroll
        for (int nt = 0; nt < 4; nt++)
            #pragma unroll
            for (int q = 0; q < 4; q++) acc[nt][q] = 0.0f;

        #pragma unroll
        for (int ks = 0; ks < 16; ks++) {
            const int k0 = ks * 8;
            unsigned a[4];
            {
                int r = wm + lr;
                a[0] = __float_as_uint(sAc[r * APITCH + k0 + lc]);
                a[1] = __float_as_uint(sAc[(r + 8) * APITCH + k0 + lc]);
                a[2] = __float_as_uint(sAc[r * APITCH + k0 + lc + 4]);
                a[3] = __float_as_uint(sAc[(r + 8) * APITCH + k0 + lc + 4]);
            }
            unsigned bfr[4][2];
            #pragma unroll
            for (int nt = 0; nt < 4; nt++) {
                int c = wn + nt * 8 + lr;
                float2 bp = sBp[ks * 512 + c * 4 + lc];   // LDS.64, conflict-free
                bfr[nt][0] = __float_as_uint(bp.x);
                bfr[nt][1] = __float_as_uint(bp.y);
            }
            #pragma unroll
            for (int nt = 0; nt < 4; nt++)
                mma_tf32(acc[nt], a, bfr[nt]);
        }

        // store this subtile
        const int m0 = mg + msub * MSUB;
        {
            int r = m0 + wm + lr;
            #pragma unroll
            for (int nt = 0; nt < 4; nt++) {
                int c = n0 + wn + nt * 8 + lc * 2;
                if (c < VV) {
                    out[(size_t)r * VV + c]       = acc[nt][0];
                    out[(size_t)(r + 8) * VV + c] = acc[nt][2];
                }
                if (c + 1 < VV) {
                    out[(size_t)r * VV + c + 1]       = acc[nt][1];
                    out[(size_t)(r + 8) * VV + c + 1] = acc[nt][3];
                }
            }
        }

        cp_wait0();
        __syncthreads();   // next iteration overwrites buf^1 only after all reads
        buf ^= 1;
    }
}

// ---------------------------------------------------------------------------
// launch
// ---------------------------------------------------------------------------
extern "C" void kernel_launch(void* const* d_in, const int* in_sizes, int n_in,
                              void* d_out, int out_size)
{
    const int*   users = (const int*)d_in[0];
    const int*   items = (const int*)d_in[1];
    const float* h0    = (const float*)d_in[2];
    const float* P_ru  = (const float*)d_in[3];
    const float* W_ru  = (const float*)d_in[4];
    const float* b_ru  = (const float*)d_in[5];
    const float* P_c   = (const float*)d_in[6];
    const float* W_c   = (const float*)d_in[7];
    const float* b_c   = (const float*)d_in[8];
    const float* ws    = (const float*)d_in[9];
    float* out = (float*)d_out;

    static_assert(RNN_SMEM_BYTES <= 232448, "rnn smem too big");
    static_assert(G_SMEM_BYTES <= 116224, "gemm smem too big for 2 CTAs/SM");

    cudaFuncSetAttribute(rnn_kernel, cudaFuncAttributeMaxDynamicSharedMemorySize,
                         RNN_SMEM_BYTES);
    cudaFuncSetAttribute(gemm_kernel, cudaFuncAttributeMaxDynamicSharedMemorySize,
                         G_SMEM_BYTES);

    rnn_kernel<<<BB, 256, RNN_SMEM_BYTES>>>(users, items, h0, P_ru, W_ru, b_ru,
                                            P_c, W_c, b_c);

    dim3 grid((VV + 127) / 128, 4);
    gemm_kernel<<<grid, 256, G_SMEM_BYTES>>>(ws, out);
}

// round 13
// speedup vs baseline: 1.9676x; 1.2155x over previous
#include <cuda_runtime.h>
#include <math.h>
#include <stdint.h>

#define BB 32
#define SS 128
#define UU 256
#define HH 128
#define VV 30001

// Scratch (__device__ globals: allocation-free rule)
__device__ float g_state[BB * UU * HH];   // per-(b,u) hidden state
__device__ float g_outs[BB * SS * HH];    // RNN outputs (tf32-rounded) = GEMM A

__device__ __forceinline__ float to_tf32(float x) {
    float r;
    asm("cvt.rna.tf32.f32 %0, %1;" : "=f"(r) : "f"(x));
    return r;
}

// f32x2 packed math (sm_103a)
__device__ __forceinline__ unsigned long long pack2(float lo, float hi) {
    unsigned long long d;
    asm("mov.b64 %0, {%1, %2};" : "=l"(d) : "f"(lo), "f"(hi));
    return d;
}
__device__ __forceinline__ void unpack2(unsigned long long v, float& lo, float& hi) {
    asm("mov.b64 {%0, %1}, %2;" : "=f"(lo), "=f"(hi) : "l"(v));
}
__device__ __forceinline__ void fma2(unsigned long long& d, unsigned long long a,
                                     unsigned long long b) {
    asm("fma.rn.f32x2 %0, %1, %2, %0;" : "+l"(d) : "l"(a), "l"(b));
}

// ===========================================================================
// RNN scan (unchanged from R8 passing version)
// ===========================================================================
#define CH 16
#define TP 20

#define RNN_F_WRU   (128 * 256)
#define RNN_F_WC    (128 * 128)
#define RNN_F_BUFS  (3 * 128 * TP)
#define RNN_INTS    (128 + 128 + 128 + 128 + 130 + 8)
#define RNN_SMEM_BYTES ((RNN_F_WRU + RNN_F_WC + 256 + 128 + RNN_F_BUFS + RNN_INTS) * 4)

__global__ __launch_bounds__(256, 1) void rnn_kernel(
    const int* __restrict__ users, const int* __restrict__ items,
    const float* __restrict__ h0,
    const float* __restrict__ P_ru, const float* __restrict__ W_ru,
    const float* __restrict__ b_ru, const float* __restrict__ P_c,
    const float* __restrict__ W_c,  const float* __restrict__ b_c)
{
    extern __shared__ float sm[];
    float* sWru = sm;
    float* sWc  = sWru + RNN_F_WRU;
    float* sbru = sWc + RNN_F_WC;
    float* sbc  = sbru + 256;
    float* sHT  = sbc + 128;
    float* sRHT = sHT + 128 * TP;
    float* sZT  = sRHT + 128 * TP;
    int*   su      = (int*)(sZT + 128 * TP);
    int*   sit     = su + 128;
    int*   slev    = sit + 128;
    int*   sorder  = slev + 128;
    int*   slstart = sorder + 128;
    int*   smisc   = slstart + 130;

    const int b   = blockIdx.x;
    const int tid = threadIdx.x;

    {
        const float4* s4 = (const float4*)W_ru;
        float4*       d4 = (float4*)sWru;
        for (int i = tid; i < RNN_F_WRU / 4; i += 256) d4[i] = s4[i];
        const float4* s4c = (const float4*)W_c;
        float4*       d4c = (float4*)sWc;
        for (int i = tid; i < RNN_F_WC / 4; i += 256) d4c[i] = s4c[i];
    }
    sbru[tid] = b_ru[tid];
    if (tid < HH) sbc[tid] = b_c[tid];

    for (int i = tid; i < 3 * 128 * TP; i += 256) sHT[i] = 0.0f;

    {
        const float4* src = (const float4*)(h0 + (size_t)b * UU * HH);
        float4*       dst = (float4*)(g_state + (size_t)b * UU * HH);
        for (int i = tid; i < UU * HH / 4; i += 256) dst[i] = src[i];
    }

    if (tid < SS) {
        su[tid]  = users[b * SS + tid];
        sit[tid] = items[b * SS + tid];
    }
    __syncthreads();

    if (tid < SS) {
        int u = su[tid], c = 0;
        for (int tp = 0; tp < tid; tp++) c += (su[tp] == u);
        slev[tid] = c;
    }
    __syncthreads();
    if (tid == 0) {
        int m = 0;
        for (int t = 0; t < SS; t++) m = max(m, slev[t]);
        smisc[0] = m + 1;
    }
    if (tid <= SS) {
        int c = 0;
        for (int t = 0; t < SS; t++) c += (slev[t] < tid);
        slstart[tid] = c;
    }
    __syncthreads();
    if (tid < SS) {
        int l = slev[tid], r = 0;
        for (int tp = 0; tp < tid; tp++) r += (slev[tp] == l);
        sorder[slstart[l] + r] = tid;
    }
    __syncthreads();

    const int maxlev = smisc[0];
    float* state_b = g_state + (size_t)b * UU * HH;
    float* out_b   = g_outs + (size_t)b * SS * HH;
    const int j = tid;

    for (int l = 0; l < maxlev; l++) {
        const int lstart = slstart[l], lend = slstart[l + 1];
        for (int cs = lstart; cs < lend; cs += CH) {
            const int n = min(CH, lend - cs);

            {
                int i      = tid & 15;
                int r4base = tid >> 4;
                if (i < n) {
                    int t = sorder[cs + i];
                    const float4* srcs = (const float4*)(state_b + su[t] * HH);
                    #pragma unroll
                    for (int rr = 0; rr < 2; rr++) {
                        int r4 = r4base + rr * 16;
                        float4 v = srcs[r4];
                        int k0 = r4 * 4;
                        sHT[(k0 + 0) * TP + i] = v.x;
                        sHT[(k0 + 1) * TP + i] = v.y;
                        sHT[(k0 + 2) * TP + i] = v.z;
                        sHT[(k0 + 3) * TP + i] = v.w;
                    }
                }
            }
            __syncthreads();

            {
                float pAdd[CH];
                #pragma unroll
                for (int i = 0; i < CH; i++) pAdd[i] = 0.0f;
                for (int i = 0; i < n; i++)
                    pAdd[i] = P_ru[(size_t)sit[sorder[cs + i]] * (2 * HH) + j];

                unsigned long long acc2[CH / 2];
                #pragma unroll
                for (int p = 0; p < CH / 2; p++) acc2[p] = 0ULL;

                #pragma unroll 4
                for (int k = 0; k < HH; k++) {
                    float w = sWru[k * 256 + j];
                    unsigned long long w2 = pack2(w, w);
                    const ulonglong2* h4 = (const ulonglong2*)(sHT + k * TP);
                    #pragma unroll
                    for (int q = 0; q < CH / 4; q++) {
                        ulonglong2 hp = h4[q];
                        fma2(acc2[2 * q],     hp.x, w2);
                        fma2(acc2[2 * q + 1], hp.y, w2);
                    }
                }

                float bj = sbru[j];
                if (j < HH) {
                    #pragma unroll
                    for (int p = 0; p < CH / 2; p++) {
                        float a0, a1;
                        unpack2(acc2[p], a0, a1);
                        float x0 = fminf(fmaxf(a0 + pAdd[2 * p] + bj,     -15.f), 15.f);
                        float x1 = fminf(fmaxf(a1 + pAdd[2 * p + 1] + bj, -15.f), 15.f);
                        float r0 = __fdividef(1.0f, 1.0f + __expf(-x0));
                        float r1 = __fdividef(1.0f, 1.0f + __expf(-x1));
                        sRHT[j * TP + 2 * p]     = r0 * sHT[j * TP + 2 * p];
                        sRHT[j * TP + 2 * p + 1] = r1 * sHT[j * TP + 2 * p + 1];
                    }
                } else {
                    int jz = j - HH;
                    #pragma unroll
                    for (int p = 0; p < CH / 2; p++) {
                        float a0, a1;
                        unpack2(acc2[p], a0, a1);
                        float x0 = fminf(fmaxf(a0 + pAdd[2 * p] + bj,     -15.f), 15.f);
                        float x1 = fminf(fmaxf(a1 + pAdd[2 * p + 1] + bj, -15.f), 15.f);
                        sZT[jz * TP + 2 * p]     = __fdividef(1.0f, 1.0f + __expf(-x0));
                        sZT[jz * TP + 2 * p + 1] = __fdividef(1.0f, 1.0f + __expf(-x1));
                    }
                }
            }
            __syncthreads();

            if (j < HH) {
                float pAdd[CH];
                #pragma unroll
                for (int i = 0; i < CH; i++) pAdd[i] = 0.0f;
                for (int i = 0; i < n; i++)
                    pAdd[i] = P_c[(size_t)sit[sorder[cs + i]] * HH + j];

                unsigned long long acc2[CH / 2];
                #pragma unroll
                for (int p = 0; p < CH / 2; p++) acc2[p] = 0ULL;

                #pragma unroll 4
                for (int k = 0; k < HH; k++) {
                    float w = sWc[k * 128 + j];
                    unsigned long long w2 = pack2(w, w);
                    const ulonglong2* r4 = (const ulonglong2*)(sRHT + k * TP);
                    #pragma unroll
                    for (int q = 0; q < CH / 4; q++) {
                        ulonglong2 rp = r4[q];
                        fma2(acc2[2 * q],     rp.x, w2);
                        fma2(acc2[2 * q + 1], rp.y, w2);
                    }
                }

                float bj = sbc[j];
                float cc[CH];
                #pragma unroll
                for (int p = 0; p < CH / 2; p++) {
                    float a0, a1;
                    unpack2(acc2[p], a0, a1);
                    float x0 = fminf(fmaxf(a0 + pAdd[2 * p] + bj,     -15.f), 15.f);
                    float x1 = fminf(fmaxf(a1 + pAdd[2 * p + 1] + bj, -15.f), 15.f);
                    float t0 = __expf(-2.0f * x0);
                    float t1 = __expf(-2.0f * x1);
                    cc[2 * p]     = __fdividef(1.0f - t0, 1.0f + t0);
                    cc[2 * p + 1] = __fdividef(1.0f - t1, 1.0f + t1);
                }
                for (int i = 0; i < n; i++) {
                    int t = sorder[cs + i];
                    float z = sZT[j * TP + i];
                    float h = sHT[j * TP + i];
                    float hn = z * h + (1.0f - z) * cc[i];
                    state_b[su[t] * HH + j] = hn;
                    out_b[(size_t)t * HH + j] = to_tf32(hn);
                }
            }
            __syncthreads();
        }
    }
}

// ===========================================================================
// Logits GEMM, mma.sync tf32 — 2 CTAs/SM + smem-staged coalesced epilogue.
//   256 threads; CTA: B 128n packed (64KB), 16 M-subtiles of 32 rows,
//   A cp.async double-buffered; accs staged to smem then stored with
//   32-consecutive-lane rows (128B contiguous per warp STG).
// ===========================================================================
#define MSUB   32
#define MSTRIP 512
#define NSUB   (MSTRIP / MSUB)           // 16 subtiles per CTA
#define APITCH 132
#define G_NB2  (16 * 512)                // B: [16ks][128c][4lc] float2 = 64 KB
#define G_A_FLOATS (2 * MSUB * APITCH)   // 33792 B
#define STPITCH 68                       // float2 pitch for stage (136 floats)
#define G_ST_F2 (16 * STPITCH)           // 16-row stage = 8704 B
#define G_SMEM_BYTES (G_NB2 * 8 + G_A_FLOATS * 4 + G_ST_F2 * 8)

__device__ __forceinline__ void cp_async16(uint32_t saddr, const void* gsrc) {
    asm volatile("cp.async.cg.shared.global [%0], [%1], 16;\n" :: "r"(saddr), "l"(gsrc));
}
__device__ __forceinline__ void cp_commit() { asm volatile("cp.async.commit_group;\n"); }
__device__ __forceinline__ void cp_wait0()  { asm volatile("cp.async.wait_group 0;\n"); }

__device__ __forceinline__ void mma_tf32(float c[4], const unsigned a[4],
                                         const unsigned bfr[2]) {
    asm volatile(
        "mma.sync.aligned.m16n8k8.row.col.f32.tf32.tf32.f32 "
        "{%0,%1,%2,%3}, {%4,%5,%6,%7}, {%8,%9}, {%0,%1,%2,%3};\n"
        : "+f"(c[0]), "+f"(c[1]), "+f"(c[2]), "+f"(c[3])
        : "r"(a[0]), "r"(a[1]), "r"(a[2]), "r"(a[3]), "r"(bfr[0]), "r"(bfr[1]));
}

__global__ __launch_bounds__(256, 2) void gemm_kernel(const float* __restrict__ ws,
                                                      float* __restrict__ out)
{
    extern __shared__ float smg[];
    float2* sBp = (float2*)smg;                       // packed B fragments
    float*  sA  = smg + G_NB2 * 2;                    // [2][MSUB][APITCH]
    float2* sSt = (float2*)(sA + G_A_FLOATS);         // [16][STPITCH] stage

    const int tid = threadIdx.x;
    const int n0  = blockIdx.x * 128;
    const int mg  = blockIdx.y * MSTRIP;

    uint32_t sA_base = (uint32_t)__cvta_generic_to_shared(sA);

    // ---- prefetch A subtile 0 ----
    {
        const float* src = g_outs + (size_t)mg * HH;
        for (int idx = tid; idx < MSUB * 32; idx += 256) {
            int row = idx >> 5, q = idx & 31;
            cp_async16(sA_base + (row * APITCH + q * 4) * 4, src + row * HH + q * 4);
        }
        cp_commit();
    }

    // ---- B load, packed fragment order, tf32-rounded in-flight ----
    for (int idx = tid; idx < 16 * 128 * 4; idx += 256) {
        int c   = idx & 127;
        int lcc = (idx >> 7) & 3;
        int ks  = idx >> 9;
        int k   = ks * 8 + lcc;
        int gn  = n0 + c;
        float v0 = 0.0f, v1 = 0.0f;
        if (gn < VV) {
            v0 = ws[(size_t)k * VV + gn];
            v1 = ws[(size_t)(k + 4) * VV + gn];
        }
        sBp[ks * 512 + c * 4 + lcc] = make_float2(to_tf32(v0), to_tf32(v1));
    }

    const int wid  = tid >> 5;
    const int lane = tid & 31;
    const int wm = (wid & 1) * 16;     // 2 warps over 32 m
    const int wn = (wid >> 1) * 32;    // 4 warps over 128 n
    const int lr = lane >> 2;
    const int lc = lane & 3;

    cp_wait0();
    __syncthreads();

    int buf = 0;
    for (int msub = 0; msub < NSUB; msub++) {
        // prefetch next A subtile into the other buffer
        if (msub < NSUB - 1) {
            const float* src = g_outs + (size_t)(mg + (msub + 1) * MSUB) * HH;
            uint32_t dstb = sA_base + (uint32_t)(buf ^ 1) * (uint32_t)MSUB * APITCH * 4u;
            for (int idx = tid; idx < MSUB * 32; idx += 256) {
                int row = idx >> 5, q = idx & 31;
                cp_async16(dstb + (row * APITCH + q * 4) * 4, src + row * HH + q * 4);
            }
            cp_commit();
        }

        float* sAc = sA + buf * MSUB * APITCH;

        float acc[4][4];
        #pragma unroll
        for (int nt = 0; nt < 4; nt++)
            #pragma unroll
            for (int q = 0; q < 4; q++) acc[nt][q] = 0.0f;

        #pragma unroll
        for (int ks = 0; ks < 16; ks++) {
            const int k0 = ks * 8;
            unsigned a[4];
            {
                int r = wm + lr;
                a[0] = __float_as_uint(sAc[r * APITCH + k0 + lc]);
                a[1] = __float_as_uint(sAc[(r + 8) * APITCH + k0 + lc]);
                a[2] = __float_as_uint(sAc[r * APITCH + k0 + lc + 4]);
                a[3] = __float_as_uint(sAc[(r + 8) * APITCH + k0 + lc + 4]);
            }
            unsigned bfr[4][2];
            #pragma unroll
            for (int nt = 0; nt < 4; nt++) {
                int c = wn + nt * 8 + lr;
                float2 bp = sBp[ks * 512 + c * 4 + lc];   // LDS.64, conflict-free
                bfr[nt][0] = __float_as_uint(bp.x);
                bfr[nt][1] = __float_as_uint(bp.y);
            }
            #pragma unroll
            for (int nt = 0; nt < 4; nt++)
                mma_tf32(acc[nt], a, bfr[nt]);
        }

        // ---- staged, coalesced epilogue: two 16-row passes ----
        const int m0 = mg + msub * MSUB;
        #pragma unroll
        for (int pass = 0; pass < 2; pass++) {
            if (wm == pass * 16) {
                #pragma unroll
                for (int nt = 0; nt < 4; nt++) {
                    int c2 = (wn >> 1) + nt * 4 + lc;
                    sSt[lr * STPITCH + c2]       = make_float2(acc[nt][0], acc[nt][1]);
                    sSt[(lr + 8) * STPITCH + c2] = make_float2(acc[nt][2], acc[nt][3]);
                }
            }
            __syncthreads();
            // 32 consecutive lanes per row -> 128B contiguous STG
            for (int idx = tid; idx < 16 * 128; idx += 256) {
                int row = idx >> 7, col = idx & 127;
                int gc = n0 + col;
                if (gc < VV) {
                    float v = ((const float*)(sSt + row * STPITCH))[col];
                    out[(size_t)(m0 + pass * 16 + row) * VV + gc] = v;
                }
            }
            __syncthreads();   // stage reusable (and, after pass 1, A buf safe)
        }

        cp_wait0();            // next A buffer landed
        buf ^= 1;
    }
}

// ---------------------------------------------------------------------------
// launch
// ---------------------------------------------------------------------------
extern "C" void kernel_launch(void* const* d_in, const int* in_sizes, int n_in,
                              void* d_out, int out_size)
{
    const int*   users = (const int*)d_in[0];
    const int*   items = (const int*)d_in[1];
    const float* h0    = (const float*)d_in[2];
    const float* P_ru  = (const float*)d_in[3];
    const float* W_ru  = (const float*)d_in[4];
    const float* b_ru  = (const float*)d_in[5];
    const float* P_c   = (const float*)d_in[6];
    const float* W_c   = (const float*)d_in[7];
    const float* b_c   = (const float*)d_in[8];
    const float* ws    = (const float*)d_in[9];
    float* out = (float*)d_out;

    static_assert(RNN_SMEM_BYTES <= 232448, "rnn smem too big");
    static_assert(G_SMEM_BYTES <= 116224, "gemm smem too big for 2 CTAs/SM");

    cudaFuncSetAttribute(rnn_kernel, cudaFuncAttributeMaxDynamicSharedMemorySize,
                         RNN_SMEM_BYTES);
    cudaFuncSetAttribute(gemm_kernel, cudaFuncAttributeMaxDynamicSharedMemorySize,
                         G_SMEM_BYTES);

    rnn_kernel<<<BB, 256, RNN_SMEM_BYTES>>>(users, items, h0, P_ru, W_ru, b_ru,
                                            P_c, W_c, b_c);

    dim3 grid((VV + 127) / 128, (BB * SS) / MSTRIP);
    gemm_kernel<<<grid, 256, G_SMEM_BYTES>>>(ws, out);
}

// round 14
// speedup vs baseline: 2.1724x; 1.1041x over previous
#include <cuda_runtime.h>
#include <math.h>
#include <stdint.h>

#define BB 32
#define SS 128
#define UU 256
#define HH 128
#define VV 30001

// Scratch (__device__ globals: allocation-free rule)
__device__ float g_state[BB * UU * HH];   // per-(b,u) hidden state
__device__ float g_outs[BB * SS * HH];    // RNN outputs (tf32-rounded) = GEMM A

__device__ __forceinline__ float to_tf32(float x) {
    float r;
    asm("cvt.rna.tf32.f32 %0, %1;" : "=f"(r) : "f"(x));
    return r;
}

// f32x2 packed math (sm_103a)
__device__ __forceinline__ unsigned long long pack2(float lo, float hi) {
    unsigned long long d;
    asm("mov.b64 %0, {%1, %2};" : "=l"(d) : "f"(lo), "f"(hi));
    return d;
}
__device__ __forceinline__ void unpack2(unsigned long long v, float& lo, float& hi) {
    asm("mov.b64 {%0, %1}, %2;" : "=f"(lo), "=f"(hi) : "l"(v));
}
__device__ __forceinline__ void fma2(unsigned long long& d, unsigned long long a,
                                     unsigned long long b) {
    asm("fma.rn.f32x2 %0, %1, %2, %0;" : "+l"(d) : "l"(a), "l"(b));
}

// ===========================================================================
// RNN scan (unchanged from R8 passing version)
// ===========================================================================
#define CH 16
#define TP 20

#define RNN_F_WRU   (128 * 256)
#define RNN_F_WC    (128 * 128)
#define RNN_F_BUFS  (3 * 128 * TP)
#define RNN_INTS    (128 + 128 + 128 + 128 + 130 + 8)
#define RNN_SMEM_BYTES ((RNN_F_WRU + RNN_F_WC + 256 + 128 + RNN_F_BUFS + RNN_INTS) * 4)

__global__ __launch_bounds__(256, 1) void rnn_kernel(
    const int* __restrict__ users, const int* __restrict__ items,
    const float* __restrict__ h0,
    const float* __restrict__ P_ru, const float* __restrict__ W_ru,
    const float* __restrict__ b_ru, const float* __restrict__ P_c,
    const float* __restrict__ W_c,  const float* __restrict__ b_c)
{
    extern __shared__ float sm[];
    float* sWru = sm;
    float* sWc  = sWru + RNN_F_WRU;
    float* sbru = sWc + RNN_F_WC;
    float* sbc  = sbru + 256;
    float* sHT  = sbc + 128;
    float* sRHT = sHT + 128 * TP;
    float* sZT  = sRHT + 128 * TP;
    int*   su      = (int*)(sZT + 128 * TP);
    int*   sit     = su + 128;
    int*   slev    = sit + 128;
    int*   sorder  = slev + 128;
    int*   slstart = sorder + 128;
    int*   smisc   = slstart + 130;

    const int b   = blockIdx.x;
    const int tid = threadIdx.x;

    {
        const float4* s4 = (const float4*)W_ru;
        float4*       d4 = (float4*)sWru;
        for (int i = tid; i < RNN_F_WRU / 4; i += 256) d4[i] = s4[i];
        const float4* s4c = (const float4*)W_c;
        float4*       d4c = (float4*)sWc;
        for (int i = tid; i < RNN_F_WC / 4; i += 256) d4c[i] = s4c[i];
    }
    sbru[tid] = b_ru[tid];
    if (tid < HH) sbc[tid] = b_c[tid];

    for (int i = tid; i < 3 * 128 * TP; i += 256) sHT[i] = 0.0f;

    {
        const float4* src = (const float4*)(h0 + (size_t)b * UU * HH);
        float4*       dst = (float4*)(g_state + (size_t)b * UU * HH);
        for (int i = tid; i < UU * HH / 4; i += 256) dst[i] = src[i];
    }

    if (tid < SS) {
        su[tid]  = users[b * SS + tid];
        sit[tid] = items[b * SS + tid];
    }
    __syncthreads();

    if (tid < SS) {
        int u = su[tid], c = 0;
        for (int tp = 0; tp < tid; tp++) c += (su[tp] == u);
        slev[tid] = c;
    }
    __syncthreads();
    if (tid == 0) {
        int m = 0;
        for (int t = 0; t < SS; t++) m = max(m, slev[t]);
        smisc[0] = m + 1;
    }
    if (tid <= SS) {
        int c = 0;
        for (int t = 0; t < SS; t++) c += (slev[t] < tid);
        slstart[tid] = c;
    }
    __syncthreads();
    if (tid < SS) {
        int l = slev[tid], r = 0;
        for (int tp = 0; tp < tid; tp++) r += (slev[tp] == l);
        sorder[slstart[l] + r] = tid;
    }
    __syncthreads();

    const int maxlev = smisc[0];
    float* state_b = g_state + (size_t)b * UU * HH;
    float* out_b   = g_outs + (size_t)b * SS * HH;
    const int j = tid;

    for (int l = 0; l < maxlev; l++) {
        const int lstart = slstart[l], lend = slstart[l + 1];
        for (int cs = lstart; cs < lend; cs += CH) {
            const int n = min(CH, lend - cs);

            {
                int i      = tid & 15;
                int r4base = tid >> 4;
                if (i < n) {
                    int t = sorder[cs + i];
                    const float4* srcs = (const float4*)(state_b + su[t] * HH);
                    #pragma unroll
                    for (int rr = 0; rr < 2; rr++) {
                        int r4 = r4base + rr * 16;
                        float4 v = srcs[r4];
                        int k0 = r4 * 4;
                        sHT[(k0 + 0) * TP + i] = v.x;
                        sHT[(k0 + 1) * TP + i] = v.y;
                        sHT[(k0 + 2) * TP + i] = v.z;
                        sHT[(k0 + 3) * TP + i] = v.w;
                    }
                }
            }
            __syncthreads();

            {
                float pAdd[CH];
                #pragma unroll
                for (int i = 0; i < CH; i++) pAdd[i] = 0.0f;
                for (int i = 0; i < n; i++)
                    pAdd[i] = P_ru[(size_t)sit[sorder[cs + i]] * (2 * HH) + j];

                unsigned long long acc2[CH / 2];
                #pragma unroll
                for (int p = 0; p < CH / 2; p++) acc2[p] = 0ULL;

                #pragma unroll 4
                for (int k = 0; k < HH; k++) {
                    float w = sWru[k * 256 + j];
                    unsigned long long w2 = pack2(w, w);
                    const ulonglong2* h4 = (const ulonglong2*)(sHT + k * TP);
                    #pragma unroll
                    for (int q = 0; q < CH / 4; q++) {
                        ulonglong2 hp = h4[q];
                        fma2(acc2[2 * q],     hp.x, w2);
                        fma2(acc2[2 * q + 1], hp.y, w2);
                    }
                }

                float bj = sbru[j];
                if (j < HH) {
                    #pragma unroll
                    for (int p = 0; p < CH / 2; p++) {
                        float a0, a1;
                        unpack2(acc2[p], a0, a1);
                        float x0 = fminf(fmaxf(a0 + pAdd[2 * p] + bj,     -15.f), 15.f);
                        float x1 = fminf(fmaxf(a1 + pAdd[2 * p + 1] + bj, -15.f), 15.f);
                        float r0 = __fdividef(1.0f, 1.0f + __expf(-x0));
                        float r1 = __fdividef(1.0f, 1.0f + __expf(-x1));
                        sRHT[j * TP + 2 * p]     = r0 * sHT[j * TP + 2 * p];
                        sRHT[j * TP + 2 * p + 1] = r1 * sHT[j * TP + 2 * p + 1];
                    }
                } else {
                    int jz = j - HH;
                    #pragma unroll
                    for (int p = 0; p < CH / 2; p++) {
                        float a0, a1;
                        unpack2(acc2[p], a0, a1);
                        float x0 = fminf(fmaxf(a0 + pAdd[2 * p] + bj,     -15.f), 15.f);
                        float x1 = fminf(fmaxf(a1 + pAdd[2 * p + 1] + bj, -15.f), 15.f);
                        sZT[jz * TP + 2 * p]     = __fdividef(1.0f, 1.0f + __expf(-x0));
                        sZT[jz * TP + 2 * p + 1] = __fdividef(1.0f, 1.0f + __expf(-x1));
                    }
                }
            }
            __syncthreads();

            if (j < HH) {
                float pAdd[CH];
                #pragma unroll
                for (int i = 0; i < CH; i++) pAdd[i] = 0.0f;
                for (int i = 0; i < n; i++)
                    pAdd[i] = P_c[(size_t)sit[sorder[cs + i]] * HH + j];

                unsigned long long acc2[CH / 2];
                #pragma unroll
                for (int p = 0; p < CH / 2; p++) acc2[p] = 0ULL;

                #pragma unroll 4
                for (int k = 0; k < HH; k++) {
                    float w = sWc[k * 128 + j];
                    unsigned long long w2 = pack2(w, w);
                    const ulonglong2* r4 = (const ulonglong2*)(sRHT + k * TP);
                    #pragma unroll
                    for (int q = 0; q < CH / 4; q++) {
                        ulonglong2 rp = r4[q];
                        fma2(acc2[2 * q],     rp.x, w2);
                        fma2(acc2[2 * q + 1], rp.y, w2);
                    }
                }

                float bj = sbc[j];
                float cc[CH];
                #pragma unroll
                for (int p = 0; p < CH / 2; p++) {
                    float a0, a1;
                    unpack2(acc2[p], a0, a1);
                    float x0 = fminf(fmaxf(a0 + pAdd[2 * p] + bj,     -15.f), 15.f);
                    float x1 = fminf(fmaxf(a1 + pAdd[2 * p + 1] + bj, -15.f), 15.f);
                    float t0 = __expf(-2.0f * x0);
                    float t1 = __expf(-2.0f * x1);
                    cc[2 * p]     = __fdividef(1.0f - t0, 1.0f + t0);
                    cc[2 * p + 1] = __fdividef(1.0f - t1, 1.0f + t1);
                }
                for (int i = 0; i < n; i++) {
                    int t = sorder[cs + i];
                    float z = sZT[j * TP + i];
                    float h = sHT[j * TP + i];
                    float hn = z * h + (1.0f - z) * cc[i];
                    state_b[su[t] * HH + j] = hn;
                    out_b[(size_t)t * HH + j] = to_tf32(hn);
                }
            }
            __syncthreads();
        }
    }
}

// ===========================================================================
// Logits GEMM, mma.sync tf32 — 2 CTAs/SM, 32m x 32n warp tiles (8B/MMA
// operand fetch), single-buffered 64m A subtile overlapped with epilogue.
//   256 threads = 8 warps as 2m x 4n over a 64m x 128n subtile.
//   B packed fragment order (64 KB); staged coalesced epilogue (4 passes).
// ===========================================================================
#define MSUB   64
#define MSTRIP 512
#define NSUB   (MSTRIP / MSUB)           // 8 subtiles per CTA
#define APITCH 132
#define G_NB2  (16 * 512)                // B: [16ks][128c][4lc] float2 = 64 KB
#define G_A_FLOATS (MSUB * APITCH)       // single buffer: 33792 B
#define STPITCH 68                       // float2 pitch for stage (136 floats)
#define G_ST_F2 (16 * STPITCH)           // 16-row stage = 8704 B
#define G_SMEM_BYTES (G_NB2 * 8 + G_A_FLOATS * 4 + G_ST_F2 * 8)

__device__ __forceinline__ void cp_async16(uint32_t saddr, const void* gsrc) {
    asm volatile("cp.async.cg.shared.global [%0], [%1], 16;\n" :: "r"(saddr), "l"(gsrc));
}
__device__ __forceinline__ void cp_commit() { asm volatile("cp.async.commit_group;\n"); }
__device__ __forceinline__ void cp_wait0()  { asm volatile("cp.async.wait_group 0;\n"); }

__device__ __forceinline__ void mma_tf32(float c[4], const unsigned a[4],
                                         const unsigned bfr[2]) {
    asm volatile(
        "mma.sync.aligned.m16n8k8.row.col.f32.tf32.tf32.f32 "
        "{%0,%1,%2,%3}, {%4,%5,%6,%7}, {%8,%9}, {%0,%1,%2,%3};\n"
        : "+f"(c[0]), "+f"(c[1]), "+f"(c[2]), "+f"(c[3])
        : "r"(a[0]), "r"(a[1]), "r"(a[2]), "r"(a[3]), "r"(bfr[0]), "r"(bfr[1]));
}

__global__ __launch_bounds__(256, 2) void gemm_kernel(const float* __restrict__ ws,
                                                      float* __restrict__ out)
{
    extern __shared__ float smg[];
    float2* sBp = (float2*)smg;                       // packed B fragments
    float*  sA  = smg + G_NB2 * 2;                    // [MSUB][APITCH]
    float2* sSt = (float2*)(sA + G_A_FLOATS);         // [16][STPITCH] stage

    const int tid = threadIdx.x;
    const int n0  = blockIdx.x * 128;
    const int mg  = blockIdx.y * MSTRIP;

    uint32_t sA_base = (uint32_t)__cvta_generic_to_shared(sA);

    // ---- prefetch A subtile 0 (64 rows x 128 k) ----
    {
        const float* src = g_outs + (size_t)mg * HH;
        for (int idx = tid; idx < MSUB * 32; idx += 256) {
            int row = idx >> 5, q = idx & 31;
            cp_async16(sA_base + (row * APITCH + q * 4) * 4, src + row * HH + q * 4);
        }
        cp_commit();
    }

    // ---- B load, packed fragment order, tf32-rounded in-flight ----
    for (int idx = tid; idx < 16 * 128 * 4; idx += 256) {
        int c   = idx & 127;
        int lcc = (idx >> 7) & 3;
        int ks  = idx >> 9;
        int k   = ks * 8 + lcc;
        int gn  = n0 + c;
        float v0 = 0.0f, v1 = 0.0f;
        if (gn < VV) {
            v0 = ws[(size_t)k * VV + gn];
            v1 = ws[(size_t)(k + 4) * VV + gn];
        }
        sBp[ks * 512 + c * 4 + lcc] = make_float2(to_tf32(v0), to_tf32(v1));
    }

    const int wid  = tid >> 5;
    const int lane = tid & 31;
    const int wm = (wid & 1) * 32;     // 2 warp rows over 64 m
    const int wn = (wid >> 1) * 32;    // 4 warps over 128 n
    const int lr = lane >> 2;
    const int lc = lane & 3;

    cp_wait0();
    __syncthreads();

    for (int msub = 0; msub < NSUB; msub++) {
        // ---- mainloop: 64m x 128n x 128k ----
        float acc[2][4][4];
        #pragma unroll
        for (int mt = 0; mt < 2; mt++)
            #pragma unroll
            for (int nt = 0; nt < 4; nt++)
                #pragma unroll
                for (int q = 0; q < 4; q++) acc[mt][nt][q] = 0.0f;

        #pragma unroll
        for (int ks = 0; ks < 16; ks++) {
            const int k0 = ks * 8;
            unsigned a[2][4];
            #pragma unroll
            for (int mt = 0; mt < 2; mt++) {
                int r = wm + mt * 16 + lr;
                a[mt][0] = __float_as_uint(sA[r * APITCH + k0 + lc]);
                a[mt][1] = __float_as_uint(sA[(r + 8) * APITCH + k0 + lc]);
                a[mt][2] = __float_as_uint(sA[r * APITCH + k0 + lc + 4]);
                a[mt][3] = __float_as_uint(sA[(r + 8) * APITCH + k0 + lc + 4]);
            }
            unsigned bfr[4][2];
            #pragma unroll
            for (int nt = 0; nt < 4; nt++) {
                int c = wn + nt * 8 + lr;
                float2 bp = sBp[ks * 512 + c * 4 + lc];   // LDS.64
                bfr[nt][0] = __float_as_uint(bp.x);
                bfr[nt][1] = __float_as_uint(bp.y);
            }
            #pragma unroll
            for (int mt = 0; mt < 2; mt++)
                #pragma unroll
                for (int nt = 0; nt < 4; nt++)
                    mma_tf32(acc[mt][nt], a[mt], bfr[nt]);
        }

        __syncthreads();   // all warps done reading sA

        // ---- kick off next A load; it overlaps the epilogue below ----
        if (msub < NSUB - 1) {
            const float* src = g_outs + (size_t)(mg + (msub + 1) * MSUB) * HH;
            for (int idx = tid; idx < MSUB * 32; idx += 256) {
                int row = idx >> 5, q = idx & 31;
                cp_async16(sA_base + (row * APITCH + q * 4) * 4, src + row * HH + q * 4);
            }
            cp_commit();
        }

        // ---- staged, coalesced epilogue: four 16-row passes ----
        const int m0 = mg + msub * MSUB;
        #pragma unroll
        for (int pass = 0; pass < 4; pass++) {
            const int pwm = (pass >> 1) * 32;   // which warp-row owns this pass
            const int pmt = pass & 1;           // which mt half
            if (wm == pwm) {
                #pragma unroll
                for (int nt = 0; nt < 4; nt++) {
                    int c2 = (wn >> 1) + nt * 4 + lc;
                    sSt[lr * STPITCH + c2]       = make_float2(acc[pmt][nt][0], acc[pmt][nt][1]);
                    sSt[(lr + 8) * STPITCH + c2] = make_float2(acc[pmt][nt][2], acc[pmt][nt][3]);
                }
            }
            __syncthreads();
            // 32 consecutive lanes per row -> 128B contiguous STG
            for (int idx = tid; idx < 16 * 128; idx += 256) {
                int row = idx >> 7, col = idx & 127;
                int gc = n0 + col;
                if (gc < VV) {
                    float v = ((const float*)(sSt + row * STPITCH))[col];
                    out[(size_t)(m0 + pass * 16 + row) * VV + gc] = v;
                }
            }
            __syncthreads();
        }

        cp_wait0();        // own async copies done...
        __syncthreads();   // ...and everyone's, before reading sA next iter
    }
}

// ---------------------------------------------------------------------------
// launch
// ---------------------------------------------------------------------------
extern "C" void kernel_launch(void* const* d_in, const int* in_sizes, int n_in,
                              void* d_out, int out_size)
{
    const int*   users = (const int*)d_in[0];
    const int*   items = (const int*)d_in[1];
    const float* h0    = (const float*)d_in[2];
    const float* P_ru  = (const float*)d_in[3];
    const float* W_ru  = (const float*)d_in[4];
    const float* b_ru  = (const float*)d_in[5];
    const float* P_c   = (const float*)d_in[6];
    const float* W_c   = (const float*)d_in[7];
    const float* b_c   = (const float*)d_in[8];
    const float* ws    = (const float*)d_in[9];
    float* out = (float*)d_out;

    static_assert(RNN_SMEM_BYTES <= 232448, "rnn smem too big");
    static_assert(G_SMEM_BYTES <= 116224, "gemm smem too big for 2 CTAs/SM");

    cudaFuncSetAttribute(rnn_kernel, cudaFuncAttributeMaxDynamicSharedMemorySize,
                         RNN_SMEM_BYTES);
    cudaFuncSetAttribute(gemm_kernel, cudaFuncAttributeMaxDynamicSharedMemorySize,
                         G_SMEM_BYTES);

    rnn_kernel<<<BB, 256, RNN_SMEM_BYTES>>>(users, items, h0, P_ru, W_ru, b_ru,
                                            P_c, W_c, b_c);

    dim3 grid((VV + 127) / 128, (BB * SS) / MSTRIP);
    gemm_kernel<<<grid, 256, G_SMEM_BYTES>>>(ws, out);
}